// round 1
// baseline (speedup 1.0000x reference)
#include <cuda_runtime.h>
#include <math.h>

static constexpr int T_STEPS = 1460;
static constexpr int G_NUM   = 5000;
static constexpr int UH_L    = 15;
static constexpr int PF      = 10;   // 1460 % 10 == 0; load-to-use distance hides DRAM latency

__global__ void __launch_bounds__(32) hmets_kernel(
    const float* __restrict__ x_phy,     // (T, G, 3)  [prcp, tmean, pet]
    const float* __restrict__ params,    // (T, G, 20) -- only t = T-1 used
    float* __restrict__ out)             // (T, G)
{
    const int g = blockIdx.x * blockDim.x + threadIdx.x;
    if (g >= G_NUM) return;

    // ---------------- parameters: sigmoid(params[T-1, g, :]) -> physical bounds ----------------
    const float* pp = params + ((long long)(T_STEPS - 1) * G_NUM + g) * 20;
    float r[20];
#pragma unroll
    for (int i = 0; i < 20; i++) r[i] = 1.0f / (1.0f + expf(-pp[i]));

    const float ddf_min = r[0]  * 20.0f;
    const float ddf_pls = r[1]  * 20.0f;
    const float Tbm     = -2.0f  + r[2]  * 5.0f;
    const float Kcum    = 0.01f  + r[3]  * 0.19f;
    const float fcmin   = r[4]  * 0.1f;
    const float fcminp  = 0.01f  + r[5]  * 0.24f;
    const float Ccum    = 0.005f + r[6]  * 0.045f;
    const float Tbf     = -5.0f  + r[7]  * 7.0f;
    const float Kf      = r[8]  * 5.0f;
    const float exp_fe  = r[9];
    const float ET_eff  = r[10] * 3.0f;
    const float c_run   = r[11];
    const float c_v2p   = 1e-5f  + r[12] * (0.02f - 1e-5f);
    const float c_vad   = r[13] * 0.1f;
    const float c_phr   = 1e-5f  + r[14] * (0.01f - 1e-5f);
    const float Vmax    = 0.001f + r[15] * (500.0f - 0.001f);

    const float a1 = 0.3f  + r[16] * (20.0f - 0.3f);
    const float b1 = 0.01f + r[17] * (5.0f  - 0.01f);
    const float a2 = 0.5f  + r[18] * (13.0f - 0.5f);
    const float b2 = 0.15f + r[19] * (1.5f  - 0.15f);

    // pre-fused constants
    const float ddf_cap = ddf_min + ddf_pls;
    const float fcsum   = fcmin + fcminp;
    const float invVmax = 1.0f / Vmax;

    // ---------------- gamma unit hydrographs (one-time, precise math) ----------------
    float uh1[UH_L], uh2[UH_L];
    {
        float s1 = 0.0f, s2 = 0.0f;
#pragma unroll
        for (int l = 0; l < UH_L; l++) {
            float tt = (float)l + 0.5f;
            float w1 = powf(tt, a1 - 1.0f) * expf(-tt / b1);
            float w2 = powf(tt, a2 - 1.0f) * expf(-tt / b2);
            uh1[l] = w1; uh2[l] = w2; s1 += w1; s2 += w2;
        }
        const float i1 = 1.0f / s1, i2 = 1.0f / s2;
#pragma unroll
        for (int l = 0; l < UH_L; l++) { uh1[l] *= i1; uh2[l] *= i2; }
    }

    // ---------------- state + conv shift-register (all compile-time indexed) ----------------
    float S = 1e-5f, W = 1e-5f, C = 1e-5f, V = 0.5f * Vmax, P = 1e-5f;
    float acc[UH_L];
#pragma unroll
    for (int l = 0; l < UH_L; l++) acc[l] = 0.0f;

    // software-pipelined forcing prefetch, depth PF
    const float* xb = x_phy + (long long)g * 3;
    float bp[PF], bt[PF], be[PF];
#pragma unroll
    for (int j = 0; j < PF; j++) {
        const float* q = xb + (long long)j * (3LL * G_NUM);
        bp[j] = q[0]; bt[j] = q[1]; be[j] = q[2];
    }
    float* ob = out + g;

    for (int tb = 0; tb < T_STEPS; tb += PF) {
#pragma unroll
        for (int j = 0; j < PF; j++) {
            const int t = tb + j;
            const float Pp = bp[j], Tt = bt[j], PE = be[j];

            // prefetch t + PF into the slot we just consumed
            const int t2 = t + PF;
            if (t2 < T_STEPS) {
                const float* q = xb + (long long)t2 * (3LL * G_NUM);
                bp[j] = q[0]; bt[j] = q[1]; be[j] = q[2];
            }

            // -------- HMETS step (matches reference op order) --------
            const float rain = (Tt >= 0.0f) ? Pp : 0.0f;
            const float snow = (Tt <  0.0f) ? Pp : 0.0f;

            const float pot_fr = Kf * __powf(fmaxf(Tbf - Tt, 1e-5f), exp_fe);
            const float fr = fminf(pot_fr, W);
            W -= fr;
            S += fr;

            const float ddf  = fminf(ddf_cap, ddf_min * (1.0f + Kcum * C));
            const float melt = fminf(fmaxf(ddf * (Tt - Tbm), 0.0f), S + snow);
            S = S + snow - melt;
            C = (S > 1e-5f) ? (C + melt) : 0.0f;

            const float wrf  = fmaxf(fcsum * (1.0f - Ccum * C), fcmin);
            const float wr   = wrf * S;
            const float wtmp = W + melt + rain;
            const float wa   = fmaxf(wtmp - wr, 0.0f);
            W = (wa > 0.0f) ? wr : wtmp;

            const float RET   = ET_eff * PE;
            const float ratio = V * invVmax;
            const float ht0   = c_run * ratio * wa;
            const float infil = fmaxf(wa - ht0 - RET, 0.0f);
            float ht1         = c_run * ratio * ratio * infil;
            const float ht2   = c_vad * V;
            const float v2p   = c_v2p * V;
            V = V + (infil - ht1) - ht2 - v2p;
            const float over  = fmaxf(V - Vmax, 0.0f);
            V -= over;
            ht1 += over;
            P += v2p;
            const float ht3 = c_phr * P;
            P -= ht3;

            // -------- fused UH convolution (scatter form) + output --------
            const float qgw = ht2 + ht3;
            ob[(long long)t * G_NUM] = acc[0] + ht0 * uh1[0] + ht1 * uh2[0] + qgw;
#pragma unroll
            for (int l = 0; l < UH_L - 1; l++)
                acc[l] = acc[l + 1] + ht0 * uh1[l + 1] + ht1 * uh2[l + 1];
            acc[UH_L - 1] = 0.0f;
        }
    }
}

extern "C" void kernel_launch(void* const* d_in, const int* in_sizes, int n_in,
                              void* d_out, int out_size) {
    const float* x_phy  = (const float*)d_in[0];
    const float* params = (const float*)d_in[1];
    float* out = (float*)d_out;
    (void)in_sizes; (void)n_in; (void)out_size;
    hmets_kernel<<<(G_NUM + 31) / 32, 32>>>(x_phy, params, out);
}